// round 1
// baseline (speedup 1.0000x reference)
#include <cuda_runtime.h>
#include <math.h>

#define NE    2048
#define FEAT  512
#define REST  8
#define HEAD  8
#define LEN   64
#define HL    (HEAD*LEN)    // 512 output rows of each projection
#define LR    (LEN*REST)    // 512 contracted dims per head
#define NCOL  (NE*REST)     // 16384 projection columns (n-major, r-minor)

// Scratch (allocation-free contract: __device__ globals)
// g_Y[p][h][n][lr] : unnormalized projections, p = 0:q 1:k 2:d   (96 MiB)
// g_S[h][n][m]     : scores, softmax'd in place                  (128 MiB)
// g_rn[p][n]       : 1/||y_p[n]||  (per-electron scalar)
__device__ float g_Y[(size_t)3 * HEAD * NE * LR];
__device__ float g_S[(size_t)HEAD * NE * NE];
__device__ float g_rn[3 * NE];

// ---------------------------------------------------------------------------
// Projection GEMM: Y[p][hl, (n,r)] = W_p[hl, f] * X[f, (n,r)]
// M=512, N=16384, K=512.  BM=BN=128, BK=16, 256 threads, 8x8 microtile.
// ---------------------------------------------------------------------------
__global__ __launch_bounds__(256) void proj_kernel(
    const float* __restrict__ x,
    const float* __restrict__ Wq,
    const float* __restrict__ Wk,
    const float* __restrict__ Wd)
{
    const int p = blockIdx.z;
    const float* __restrict__ W = (p == 0) ? Wq : (p == 1) ? Wk : Wd;
    const int m0 = blockIdx.y * 128;   // hl
    const int n0 = blockIdx.x * 128;   // col = n*8 + r
    const int tid = threadIdx.x;
    const int tx = tid & 15, ty = tid >> 4;

    __shared__ float As[16][128];
    __shared__ float Bs[16][128];

    float acc[8][8];
#pragma unroll
    for (int i = 0; i < 8; i++)
#pragma unroll
        for (int j = 0; j < 8; j++) acc[i][j] = 0.f;

    for (int k0 = 0; k0 < FEAT; k0 += 16) {
        // A tile: W[m0+m, k0+kk], rows contiguous in k
#pragma unroll
        for (int i = 0; i < 2; i++) {
            int v = tid + i * 256;          // 0..511
            int m = v >> 2;
            int kk = (v & 3) * 4;
            float4 t = *(const float4*)&W[(size_t)(m0 + m) * FEAT + k0 + kk];
            As[kk + 0][m] = t.x; As[kk + 1][m] = t.y;
            As[kk + 2][m] = t.z; As[kk + 3][m] = t.w;
        }
        // B tile: Bs[kk][c] = x[n, k0+kk, r], n = n0/8 + c/8, r = c%8
#pragma unroll
        for (int i = 0; i < 2; i++) {
            int v = tid + i * 256;          // 0..511
            int kk = v >> 5;                // 0..15
            int c4 = v & 31;                // c = c4*4
            int n  = (n0 >> 3) + (c4 >> 1);
            int rb = (c4 & 1) * 4;
            float4 t = *(const float4*)&x[(size_t)n * (FEAT * REST) + (k0 + kk) * REST + rb];
            int c = c4 * 4;
            Bs[kk][c + 0] = t.x; Bs[kk][c + 1] = t.y;
            Bs[kk][c + 2] = t.z; Bs[kk][c + 3] = t.w;
        }
        __syncthreads();
#pragma unroll
        for (int k = 0; k < 16; k++) {
            float a[8], b[8];
#pragma unroll
            for (int i = 0; i < 8; i++) a[i] = As[k][ty * 8 + i];
#pragma unroll
            for (int j = 0; j < 8; j++) b[j] = Bs[k][tx * 8 + j];
#pragma unroll
            for (int i = 0; i < 8; i++)
#pragma unroll
                for (int j = 0; j < 8; j++) acc[i][j] += a[i] * b[j];
        }
        __syncthreads();
    }
    // epilogue: Y[p][h][n][l*8+r]
#pragma unroll
    for (int i = 0; i < 8; i++) {
        int row = m0 + ty * 8 + i;
        int h = row >> 6, l = row & 63;
#pragma unroll
        for (int j = 0; j < 8; j++) {
            int col = n0 + tx * 8 + j;
            int n = col >> 3, r = col & 7;
            g_Y[(((size_t)p * HEAD + h) * NE + n) * LR + l * REST + r] = acc[i][j];
        }
    }
}

// ---------------------------------------------------------------------------
// Per-electron inverse norms: g_rn[p][n] = 1/sqrt(sum over h,lr of Y^2)
// ---------------------------------------------------------------------------
__global__ __launch_bounds__(256) void norm_kernel()
{
    const int n = blockIdx.x;
    const int p = blockIdx.y;
    const float* base = &g_Y[((size_t)p * HEAD) * NE * LR + (size_t)n * LR];
    float s = 0.f;
#pragma unroll
    for (int h = 0; h < HEAD; h++) {
        const float* rp = base + (size_t)h * NE * LR;
        for (int j = threadIdx.x; j < LR; j += 256) {
            float v = rp[j];
            s += v * v;
        }
    }
    __shared__ float red[256];
    red[threadIdx.x] = s;
    __syncthreads();
    for (int off = 128; off > 0; off >>= 1) {
        if (threadIdx.x < off) red[threadIdx.x] += red[threadIdx.x + off];
        __syncthreads();
    }
    if (threadIdx.x == 0) g_rn[p * NE + n] = 1.0f / sqrtf(red[0]);
}

// ---------------------------------------------------------------------------
// Scores (NT GEMM per head): S[h][n][m] = rn_q[n]*rn_k[m] * sum_k Q[n,k]*K[m,k]
// M=N=2048, K=512
// ---------------------------------------------------------------------------
__global__ __launch_bounds__(256) void scores_kernel()
{
    const int h = blockIdx.z;
    const float* __restrict__ A = &g_Y[((size_t)0 * HEAD + h) * NE * LR];
    const float* __restrict__ B = &g_Y[((size_t)1 * HEAD + h) * NE * LR];
    const int m0 = blockIdx.y * 128;   // n
    const int n0 = blockIdx.x * 128;   // m
    const int tid = threadIdx.x;
    const int tx = tid & 15, ty = tid >> 4;

    __shared__ float As[16][128];
    __shared__ float Bs[16][128];

    float acc[8][8];
#pragma unroll
    for (int i = 0; i < 8; i++)
#pragma unroll
        for (int j = 0; j < 8; j++) acc[i][j] = 0.f;

    for (int k0 = 0; k0 < LR; k0 += 16) {
#pragma unroll
        for (int i = 0; i < 2; i++) {
            int v = tid + i * 256;
            int m = v >> 2;
            int kk = (v & 3) * 4;
            float4 t = *(const float4*)&A[(size_t)(m0 + m) * LR + k0 + kk];
            As[kk + 0][m] = t.x; As[kk + 1][m] = t.y;
            As[kk + 2][m] = t.z; As[kk + 3][m] = t.w;
        }
#pragma unroll
        for (int i = 0; i < 2; i++) {
            int v = tid + i * 256;
            int c = v >> 2;
            int kk = (v & 3) * 4;
            float4 t = *(const float4*)&B[(size_t)(n0 + c) * LR + k0 + kk];
            Bs[kk + 0][c] = t.x; Bs[kk + 1][c] = t.y;
            Bs[kk + 2][c] = t.z; Bs[kk + 3][c] = t.w;
        }
        __syncthreads();
#pragma unroll
        for (int k = 0; k < 16; k++) {
            float a[8], b[8];
#pragma unroll
            for (int i = 0; i < 8; i++) a[i] = As[k][ty * 8 + i];
#pragma unroll
            for (int j = 0; j < 8; j++) b[j] = Bs[k][tx * 8 + j];
#pragma unroll
            for (int i = 0; i < 8; i++)
#pragma unroll
                for (int j = 0; j < 8; j++) acc[i][j] += a[i] * b[j];
        }
        __syncthreads();
    }
    float rq[8], rk[8];
#pragma unroll
    for (int i = 0; i < 8; i++) rq[i] = g_rn[0 * NE + m0 + ty * 8 + i];
#pragma unroll
    for (int j = 0; j < 8; j++) rk[j] = g_rn[1 * NE + n0 + tx * 8 + j];
#pragma unroll
    for (int i = 0; i < 8; i++) {
        int row = m0 + ty * 8 + i;
#pragma unroll
        for (int j = 0; j < 8; j++) {
            int col = n0 + tx * 8 + j;
            g_S[((size_t)h * NE + row) * NE + col] = acc[i][j] * rq[i] * rk[j];
        }
    }
}

// ---------------------------------------------------------------------------
// Softmax over m (in place), folding 1/||d_m|| into the weights
// ---------------------------------------------------------------------------
__global__ __launch_bounds__(256) void softmax_kernel()
{
    const int n = blockIdx.x;
    const int h = blockIdx.y;
    float* row = &g_S[((size_t)h * NE + n) * NE];
    const int tid = threadIdx.x;

    float e[8];
    float mx = -1e30f;
#pragma unroll
    for (int i = 0; i < 8; i++) {
        e[i] = row[tid + i * 256];
        mx = fmaxf(mx, e[i]);
    }
    __shared__ float red[256];
    red[tid] = mx;
    __syncthreads();
    for (int off = 128; off > 0; off >>= 1) {
        if (tid < off) red[tid] = fmaxf(red[tid], red[tid + off]);
        __syncthreads();
    }
    mx = red[0];
    __syncthreads();

    float s = 0.f;
#pragma unroll
    for (int i = 0; i < 8; i++) {
        e[i] = __expf(e[i] - mx);
        s += e[i];
    }
    red[tid] = s;
    __syncthreads();
    for (int off = 128; off > 0; off >>= 1) {
        if (tid < off) red[tid] += red[tid + off];
        __syncthreads();
    }
    float inv = 1.0f / red[0];
#pragma unroll
    for (int i = 0; i < 8; i++) {
        int col = tid + i * 256;
        row[col] = e[i] * inv * g_rn[2 * NE + col];
    }
}

// ---------------------------------------------------------------------------
// Combine (NN GEMM per head): out[n, h*512+lr] = sum_m W[h][n][m] * D[h][m][lr]
// M=2048, N=512, K=2048
// ---------------------------------------------------------------------------
__global__ __launch_bounds__(256) void combine_kernel(float* __restrict__ out)
{
    const int h = blockIdx.z;
    const float* __restrict__ A = &g_S[(size_t)h * NE * NE];
    const float* __restrict__ B = &g_Y[((size_t)2 * HEAD + h) * NE * LR];
    const int m0 = blockIdx.y * 128;   // n
    const int n0 = blockIdx.x * 128;   // lr
    const int tid = threadIdx.x;
    const int tx = tid & 15, ty = tid >> 4;

    __shared__ float As[16][128];
    __shared__ float Bs[16][128];

    float acc[8][8];
#pragma unroll
    for (int i = 0; i < 8; i++)
#pragma unroll
        for (int j = 0; j < 8; j++) acc[i][j] = 0.f;

    for (int k0 = 0; k0 < NE; k0 += 16) {
#pragma unroll
        for (int i = 0; i < 2; i++) {
            int v = tid + i * 256;
            int m = v >> 2;
            int kk = (v & 3) * 4;
            float4 t = *(const float4*)&A[(size_t)(m0 + m) * NE + k0 + kk];
            As[kk + 0][m] = t.x; As[kk + 1][m] = t.y;
            As[kk + 2][m] = t.z; As[kk + 3][m] = t.w;
        }
#pragma unroll
        for (int i = 0; i < 2; i++) {
            int v = tid + i * 256;
            int kk = v >> 5;
            int c4 = v & 31;
            float4 t = *(const float4*)&B[(size_t)(k0 + kk) * LR + n0 + c4 * 4];
            int c = c4 * 4;
            Bs[kk][c + 0] = t.x; Bs[kk][c + 1] = t.y;
            Bs[kk][c + 2] = t.z; Bs[kk][c + 3] = t.w;
        }
        __syncthreads();
#pragma unroll
        for (int k = 0; k < 16; k++) {
            float a[8], b[8];
#pragma unroll
            for (int i = 0; i < 8; i++) a[i] = As[k][ty * 8 + i];
#pragma unroll
            for (int j = 0; j < 8; j++) b[j] = Bs[k][tx * 8 + j];
#pragma unroll
            for (int i = 0; i < 8; i++)
#pragma unroll
                for (int j = 0; j < 8; j++) acc[i][j] += a[i] * b[j];
        }
        __syncthreads();
    }
#pragma unroll
    for (int i = 0; i < 8; i++) {
        int n = m0 + ty * 8 + i;
#pragma unroll
        for (int j = 0; j < 8; j++) {
            int lr = n0 + tx * 8 + j;
            out[(size_t)n * (HEAD * LR) + h * LR + lr] = acc[i][j];
        }
    }
}

// ---------------------------------------------------------------------------
extern "C" void kernel_launch(void* const* d_in, const int* in_sizes, int n_in,
                              void* d_out, int out_size)
{
    const float* x  = (const float*)d_in[0];
    const float* Wq = (const float*)d_in[1];
    const float* Wk = (const float*)d_in[2];
    const float* Wd = (const float*)d_in[3];
    float* out = (float*)d_out;

    dim3 gp(NCOL / 128, HL / 128, 3);
    proj_kernel<<<gp, 256>>>(x, Wq, Wk, Wd);

    dim3 gn(NE, 3);
    norm_kernel<<<gn, 256>>>();

    dim3 gs(NE / 128, NE / 128, HEAD);
    scores_kernel<<<gs, 256>>>();

    dim3 gsm(NE, HEAD);
    softmax_kernel<<<gsm, 256>>>();

    dim3 gc(LR / 128, NE / 128, HEAD);
    combine_kernel<<<gc, 256>>>(out);
}

// round 3
// speedup vs baseline: 2.2695x; 2.2695x over previous
#include <cuda_runtime.h>
#include <math.h>
#include <stdint.h>

#define NE    2048
#define FEAT  512
#define REST  8
#define HEAD  8
#define HL    512
#define NCOL  16384
#define OUTC  (HEAD*512)
#define BK    16
#define PAD   20          // row stride in floats (20g+tg distinct mod 32 -> conflict-free)

// ---------------- scratch (__device__ globals; allocation-free) -------------
__device__ float g_Y  [(size_t)2 * HEAD * NE * 512];  // q,k: [(p*8+h)][n][lr]
__device__ float g_Yd2[(size_t)HEAD * 512 * NE];      // d:   [h][lr][m] (K-major for combine)
__device__ float g_xt [(size_t)NCOL * FEAT];          // xt[(n*8+r)][f]
__device__ float g_S  [(size_t)HEAD * NE * NE];       // scores / weights
__device__ float g_rn [3 * NE];

// ---------------- helpers ---------------------------------------------------
__device__ __forceinline__ uint32_t smem_u32(const void* p) {
    uint32_t a;
    asm("{ .reg .u64 t; cvta.to.shared.u64 t, %1; cvt.u32.u64 %0, t; }" : "=r"(a) : "l"(p));
    return a;
}
__device__ __forceinline__ uint32_t f2tf(float f) {
    uint32_t u;
    asm("cvt.rna.tf32.f32 %0, %1;" : "=r"(u) : "f"(f));
    return u;
}
__device__ __forceinline__ void mma8(float* c, const uint32_t* a, const uint32_t* b) {
    asm volatile(
        "mma.sync.aligned.m16n8k8.row.col.f32.tf32.tf32.f32 "
        "{%0,%1,%2,%3}, {%4,%5,%6,%7}, {%8,%9}, {%0,%1,%2,%3};"
        : "+f"(c[0]), "+f"(c[1]), "+f"(c[2]), "+f"(c[3])
        : "r"(a[0]), "r"(a[1]), "r"(a[2]), "r"(a[3]), "r"(b[0]), "r"(b[1]));
}
__device__ __forceinline__ void cp16(uint32_t dst, const float* src) {
    uint64_t g;
    asm("cvta.to.global.u64 %0, %1;" : "=l"(g) : "l"(src));
    asm volatile("cp.async.cg.shared.global [%0], [%1], 16;" :: "r"(dst), "l"(g));
}

// load 128 x 16 fp32 tile into smem[128][PAD]
__device__ __forceinline__ void ld_tile(float (*S)[PAD], const float* gp, int ldk, int k0, int tid) {
#pragma unroll
    for (int i = 0; i < 2; i++) {
        int idx = tid + i * 256;          // 0..511
        int row = idx >> 2, ch = idx & 3;
        cp16(smem_u32(&S[row][ch * 4]), gp + (size_t)row * ldk + k0 + ch * 4);
    }
}

// ---------------- tf32 NT GEMM mainloop: acc += A(128xK) * B(128xK)^T -------
// acc[2][8][4] per thread; returns nothing (acc by ref)
struct Frag { float acc[2][8][4]; };

__device__ __forceinline__ void gemm_main(Frag& F, const float* A, const float* B, int K,
                                          float (*As)[128][PAD], float (*Bs)[128][PAD]) {
    const int tid = threadIdx.x;
    const int lane = tid & 31, wid = tid >> 5;
    const int g8 = lane >> 2, tg = lane & 3;
    const int wm = (wid & 3) * 32, wn = (wid >> 2) * 64;

#pragma unroll
    for (int mt = 0; mt < 2; mt++)
#pragma unroll
        for (int nt = 0; nt < 8; nt++)
#pragma unroll
            for (int j = 0; j < 4; j++) F.acc[mt][nt][j] = 0.f;

    ld_tile(As[0], A, K, 0, tid);
    ld_tile(Bs[0], B, K, 0, tid);
    asm volatile("cp.async.commit_group;" ::: "memory");

    const int KT = K / BK;
    for (int kt = 0; kt < KT; kt++) {
        int buf = kt & 1;
        if (kt + 1 < KT) {
            ld_tile(As[buf ^ 1], A, K, (kt + 1) * BK, tid);
            ld_tile(Bs[buf ^ 1], B, K, (kt + 1) * BK, tid);
            asm volatile("cp.async.commit_group;" ::: "memory");
            asm volatile("cp.async.wait_group 1;" ::: "memory");
        } else {
            asm volatile("cp.async.wait_group 0;" ::: "memory");
        }
        __syncthreads();

#pragma unroll
        for (int ks = 0; ks < 2; ks++) {
            const int k0 = ks * 8;
            uint32_t af[2][4], bf[8][2];
#pragma unroll
            for (int mt = 0; mt < 2; mt++) {
                int r0 = wm + mt * 16 + g8;
                af[mt][0] = f2tf(As[buf][r0][k0 + tg]);
                af[mt][1] = f2tf(As[buf][r0 + 8][k0 + tg]);
                af[mt][2] = f2tf(As[buf][r0][k0 + tg + 4]);
                af[mt][3] = f2tf(As[buf][r0 + 8][k0 + tg + 4]);
            }
#pragma unroll
            for (int nt = 0; nt < 8; nt++) {
                int rn = wn + nt * 8 + g8;
                bf[nt][0] = f2tf(Bs[buf][rn][k0 + tg]);
                bf[nt][1] = f2tf(Bs[buf][rn][k0 + tg + 4]);
            }
#pragma unroll
            for (int mt = 0; mt < 2; mt++)
#pragma unroll
                for (int nt = 0; nt < 8; nt++)
                    mma8(F.acc[mt][nt], af[mt], bf[nt]);
        }
        __syncthreads();
    }
}

// ---------------- transpose x -> xt[(n*8+r)][f] -----------------------------
__global__ __launch_bounds__(256) void transpose_x(const float* __restrict__ x) {
    __shared__ float s[512 * 9];
    const int n = blockIdx.x, tid = threadIdx.x;
    const float* src = x + (size_t)n * 4096;
#pragma unroll
    for (int i = 0; i < 4; i++) {
        int v = (tid + i * 256) * 4;
        float4 t = *(const float4*)(src + v);
        int f = v >> 3, rr = v & 7;
        s[f * 9 + rr + 0] = t.x; s[f * 9 + rr + 1] = t.y;
        s[f * 9 + rr + 2] = t.z; s[f * 9 + rr + 3] = t.w;
    }
    __syncthreads();
#pragma unroll
    for (int rr = 0; rr < 8; rr++)
#pragma unroll
        for (int q = 0; q < 2; q++) {
            int f = tid + q * 256;
            g_xt[((size_t)n * 8 + rr) * 512 + f] = s[f * 9 + rr];
        }
}

// ---------------- projection GEMM -------------------------------------------
__global__ __launch_bounds__(256) void proj_tc(const float* __restrict__ Wq,
                                               const float* __restrict__ Wk,
                                               const float* __restrict__ Wd) {
    __shared__ float As[2][128][PAD], Bs[2][128][PAD];
    const int p = blockIdx.z;
    const float* W = (p == 0) ? Wq : (p == 1) ? Wk : Wd;
    const int m0 = blockIdx.y * 128, c0 = blockIdx.x * 128;

    Frag F;
    gemm_main(F, W + (size_t)m0 * FEAT, g_xt + (size_t)c0 * FEAT, FEAT, As, Bs);

    const int tid = threadIdx.x, lane = tid & 31, wid = tid >> 5;
    const int g8 = lane >> 2, tg = lane & 3;
    const int wm = (wid & 3) * 32, wn = (wid >> 2) * 64;

#pragma unroll
    for (int mt = 0; mt < 2; mt++) {
#pragma unroll
        for (int half = 0; half < 2; half++) {
            int row = m0 + wm + mt * 16 + g8 + half * 8;
            int hh = row >> 6, l = row & 63;
#pragma unroll
            for (int nt = 0; nt < 8; nt++) {
                int col = c0 + wn + nt * 8 + 2 * tg;
                float v0 = F.acc[mt][nt][half * 2 + 0];
                float v1 = F.acc[mt][nt][half * 2 + 1];
                if (p < 2) {
                    int n = col >> 3, r = col & 7;
                    float* d = g_Y + ((size_t)(p * HEAD + hh) * NE + n) * 512 + l * 8 + r;
                    *(float2*)d = make_float2(v0, v1);
                } else {
                    int n = col >> 3, r = col & 7;
                    g_Yd2[((size_t)hh * 512 + l * 8 + r)     * NE + n] = v0;
                    g_Yd2[((size_t)hh * 512 + l * 8 + r + 1) * NE + n] = v1;
                }
            }
        }
    }
}

// ---------------- norms ------------------------------------------------------
__global__ __launch_bounds__(256) void norm_qk() {
    const int n = blockIdx.x, p = blockIdx.y;
    float s = 0.f;
#pragma unroll
    for (int h = 0; h < HEAD; h++) {
        const float* rp = g_Y + ((size_t)(p * HEAD + h) * NE + n) * 512;
        for (int j = threadIdx.x; j < 512; j += 256) { float v = rp[j]; s += v * v; }
    }
    __shared__ float red[256];
    red[threadIdx.x] = s;
    __syncthreads();
    for (int off = 128; off > 0; off >>= 1) {
        if (threadIdx.x < off) red[threadIdx.x] += red[threadIdx.x + off];
        __syncthreads();
    }
    if (threadIdx.x == 0) g_rn[p * NE + n] = rsqrtf(red[0]);
}
__global__ __launch_bounds__(256) void norm_d() {
    const int n = blockIdx.x * 256 + threadIdx.x;
    float s0 = 0.f, s1 = 0.f, s2 = 0.f, s3 = 0.f;
    for (int row = 0; row < 4096; row += 4) {
        float v0 = g_Yd2[(size_t)(row + 0) * NE + n];
        float v1 = g_Yd2[(size_t)(row + 1) * NE + n];
        float v2 = g_Yd2[(size_t)(row + 2) * NE + n];
        float v3 = g_Yd2[(size_t)(row + 3) * NE + n];
        s0 += v0 * v0; s1 += v1 * v1; s2 += v2 * v2; s3 += v3 * v3;
    }
    g_rn[2 * NE + n] = rsqrtf((s0 + s1) + (s2 + s3));
}

// ---------------- scores GEMM ------------------------------------------------
__global__ __launch_bounds__(256) void scores_tc() {
    __shared__ float As[2][128][PAD], Bs[2][128][PAD];
    const int h = blockIdx.z;
    const int m0 = blockIdx.y * 128, n0 = blockIdx.x * 128;
    const float* A = g_Y + ((size_t)(0 * HEAD + h) * NE + m0) * 512;
    const float* B = g_Y + ((size_t)(1 * HEAD + h) * NE + n0) * 512;

    Frag F;
    gemm_main(F, A, B, 512, As, Bs);

    const int tid = threadIdx.x, lane = tid & 31, wid = tid >> 5;
    const int g8 = lane >> 2, tg = lane & 3;
    const int wm = (wid & 3) * 32, wn = (wid >> 2) * 64;

#pragma unroll
    for (int mt = 0; mt < 2; mt++) {
#pragma unroll
        for (int half = 0; half < 2; half++) {
            int row = m0 + wm + mt * 16 + g8 + half * 8;
            float rq = g_rn[row];
#pragma unroll
            for (int nt = 0; nt < 8; nt++) {
                int col = n0 + wn + nt * 8 + 2 * tg;
                float v0 = F.acc[mt][nt][half * 2 + 0] * rq * g_rn[NE + col];
                float v1 = F.acc[mt][nt][half * 2 + 1] * rq * g_rn[NE + col + 1];
                *(float2*)(g_S + ((size_t)h * NE + row) * NE + col) = make_float2(v0, v1);
            }
        }
    }
}

// ---------------- softmax (folds 1/||d_m||) ---------------------------------
__global__ __launch_bounds__(256) void softmax_kernel() {
    const int n = blockIdx.x, h = blockIdx.y;
    float* row = &g_S[((size_t)h * NE + n) * NE];
    const int tid = threadIdx.x;
    float e[8];
    float mx = -1e30f;
#pragma unroll
    for (int i = 0; i < 8; i++) { e[i] = row[tid + i * 256]; mx = fmaxf(mx, e[i]); }
    __shared__ float red[256];
    red[tid] = mx; __syncthreads();
    for (int off = 128; off > 0; off >>= 1) {
        if (tid < off) red[tid] = fmaxf(red[tid], red[tid + off]);
        __syncthreads();
    }
    mx = red[0]; __syncthreads();
    float s = 0.f;
#pragma unroll
    for (int i = 0; i < 8; i++) { e[i] = __expf(e[i] - mx); s += e[i]; }
    red[tid] = s; __syncthreads();
    for (int off = 128; off > 0; off >>= 1) {
        if (tid < off) red[tid] += red[tid + off];
        __syncthreads();
    }
    float inv = 1.0f / red[0];
#pragma unroll
    for (int i = 0; i < 8; i++) {
        int col = tid + i * 256;
        row[col] = e[i] * inv * g_rn[2 * NE + col];
    }
}

// ---------------- combine GEMM ----------------------------------------------
__global__ __launch_bounds__(256) void combine_tc(float* __restrict__ out) {
    __shared__ float As[2][128][PAD], Bs[2][128][PAD];
    const int h = blockIdx.z;
    const int m0 = blockIdx.y * 128, lr0 = blockIdx.x * 128;
    const float* A = g_S + ((size_t)h * NE + m0) * NE;
    const float* B = g_Yd2 + ((size_t)h * 512 + lr0) * NE;

    Frag F;
    gemm_main(F, A, B, NE, As, Bs);

    const int tid = threadIdx.x, lane = tid & 31, wid = tid >> 5;
    const int g8 = lane >> 2, tg = lane & 3;
    const int wm = (wid & 3) * 32, wn = (wid >> 2) * 64;

#pragma unroll
    for (int mt = 0; mt < 2; mt++) {
#pragma unroll
        for (int half = 0; half < 2; half++) {
            int row = m0 + wm + mt * 16 + g8 + half * 8;
#pragma unroll
            for (int nt = 0; nt < 8; nt++) {
                int col = lr0 + wn + nt * 8 + 2 * tg;
                float v0 = F.acc[mt][nt][half * 2 + 0];
                float v1 = F.acc[mt][nt][half * 2 + 1];
                *(float2*)(out + (size_t)row * OUTC + h * 512 + col) = make_float2(v0, v1);
            }
        }
    }
}

// ---------------------------------------------------------------------------
extern "C" void kernel_launch(void* const* d_in, const int* in_sizes, int n_in,
                              void* d_out, int out_size) {
    const float* x  = (const float*)d_in[0];
    const float* Wq = (const float*)d_in[1];
    const float* Wk = (const float*)d_in[2];
    const float* Wd = (const float*)d_in[3];
    float* out = (float*)d_out;

    transpose_x<<<NE, 256>>>(x);
    proj_tc<<<dim3(NCOL / 128, HL / 128, 3), 256>>>(Wq, Wk, Wd);
    norm_qk<<<dim3(NE, 2), 256>>>();
    norm_d<<<NE / 256, 256>>>();
    scores_tc<<<dim3(NE / 128, NE / 128, HEAD), 256>>>();
    softmax_kernel<<<dim3(NE, HEAD), 256>>>();
    combine_tc<<<dim3(512 / 128, NE / 128, HEAD), 256>>>(out);
}

// round 4
// speedup vs baseline: 3.5563x; 1.5670x over previous
#include <cuda_runtime.h>
#include <math.h>
#include <stdint.h>

#define NE    2048
#define FEAT  512
#define REST  8
#define HEAD  8
#define HL    512
#define NCOL  16384
#define OUTC  (HEAD*512)
#define BK    16
#define PADK  20      // K-major tile row stride (20g+tg distinct mod 32)
#define PADN  136     // MN-major tile row stride (8tg+g8 distinct mod 32)

// ---------------- scratch ----------------------------------------------------
__device__ float g_Y  [(size_t)3 * HEAD * NE * 512];  // [p][h][n][lr], tf32-rounded
__device__ float g_xt [(size_t)NCOL * FEAT];          // xt[(n*8+r)][f], rounded
__device__ float g_W  [(size_t)3 * HL * FEAT];        // rounded weights
__device__ float g_S  [(size_t)HEAD * NE * NE];       // scores -> rounded weights
__device__ float g_rn [3 * NE];

// ---------------- helpers ----------------------------------------------------
__device__ __forceinline__ uint32_t smem_u32(const void* p) {
    uint32_t a;
    asm("{ .reg .u64 t; cvta.to.shared.u64 t, %1; cvt.u32.u64 %0, t; }" : "=r"(a) : "l"(p));
    return a;
}
__device__ __forceinline__ float f2tf(float f) {
    uint32_t u;
    asm("cvt.rna.tf32.f32 %0, %1;" : "=r"(u) : "f"(f));
    return __uint_as_float(u);
}
__device__ __forceinline__ void mma8(float* c, const uint32_t* a, const uint32_t* b) {
    asm volatile(
        "mma.sync.aligned.m16n8k8.row.col.f32.tf32.tf32.f32 "
        "{%0,%1,%2,%3}, {%4,%5,%6,%7}, {%8,%9}, {%0,%1,%2,%3};"
        : "+f"(c[0]), "+f"(c[1]), "+f"(c[2]), "+f"(c[3])
        : "r"(a[0]), "r"(a[1]), "r"(a[2]), "r"(a[3]), "r"(b[0]), "r"(b[1]));
}
__device__ __forceinline__ void cp16(uint32_t dst, const float* src) {
    uint64_t g;
    asm("cvta.to.global.u64 %0, %1;" : "=l"(g) : "l"(src));
    asm volatile("cp.async.cg.shared.global [%0], [%1], 16;" :: "r"(dst), "l"(g));
}
__device__ __forceinline__ uint32_t fb(float f) { return __float_as_uint(f); }

// 128 rows x 16 K-major tile (row stride ldk in gmem)
__device__ __forceinline__ void ld_k(float (*S)[PADK], const float* gp, int ldk, int k0, int tid) {
#pragma unroll
    for (int i = 0; i < 4; i++) {
        int idx = tid + i * 128;
        int row = idx >> 2, ch = idx & 3;
        cp16(smem_u32(&S[row][ch * 4]), gp + (size_t)row * ldk + k0 + ch * 4);
    }
}
// 16 k-rows x 128 n-cols MN-major tile (gp pre-offset to n0; row stride ldn)
__device__ __forceinline__ void ld_mn(float (*S)[PADN], const float* gp, int ldn, int k0, int tid) {
#pragma unroll
    for (int i = 0; i < 4; i++) {
        int idx = tid + i * 128;
        int kk = idx >> 5, ch = idx & 31;
        cp16(smem_u32(&S[kk][ch * 4]), gp + (size_t)(k0 + kk) * ldn + ch * 4);
    }
}

struct Acc { float a[4][8][4]; };

// ---------------- mainloops (128x128 block, 4 warps of 64x64) ----------------
// BMN=0: B K-major rows [n][k]; BMN=1: B MN-major [k][n]
template<int BMN>
__device__ __forceinline__ void gemm_main(Acc& F, const float* A, const float* B,
                                          int K, int ldb,
                                          float (*As)[128][PADK],
                                          float (*BsK)[128][PADK],
                                          float (*BsN)[BK][PADN]) {
    const int tid = threadIdx.x;
    const int lane = tid & 31, wid = tid >> 5;
    const int g8 = lane >> 2, tg = lane & 3;
    const int wm = (wid & 1) * 64, wn = (wid >> 1) * 64;

#pragma unroll
    for (int mt = 0; mt < 4; mt++)
#pragma unroll
        for (int nt = 0; nt < 8; nt++)
#pragma unroll
            for (int j = 0; j < 4; j++) F.a[mt][nt][j] = 0.f;

    ld_k(As[0], A, K, 0, tid);
    if (BMN) ld_mn(BsN[0], B, ldb, 0, tid); else ld_k(BsK[0], B, K, 0, tid);
    asm volatile("cp.async.commit_group;" ::: "memory");

    const int KT = K / BK;
    for (int kt = 0; kt < KT; kt++) {
        int buf = kt & 1;
        if (kt + 1 < KT) {
            ld_k(As[buf ^ 1], A, K, (kt + 1) * BK, tid);
            if (BMN) ld_mn(BsN[buf ^ 1], B, ldb, (kt + 1) * BK, tid);
            else     ld_k(BsK[buf ^ 1], B, K, (kt + 1) * BK, tid);
            asm volatile("cp.async.commit_group;" ::: "memory");
            asm volatile("cp.async.wait_group 1;" ::: "memory");
        } else {
            asm volatile("cp.async.wait_group 0;" ::: "memory");
        }
        __syncthreads();

#pragma unroll
        for (int ks = 0; ks < 2; ks++) {
            const int k0 = ks * 8;
            uint32_t af[4][4], bf[8][2];
#pragma unroll
            for (int mt = 0; mt < 4; mt++) {
                int r0 = wm + mt * 16 + g8;
                af[mt][0] = fb(As[buf][r0][k0 + tg]);
                af[mt][1] = fb(As[buf][r0 + 8][k0 + tg]);
                af[mt][2] = fb(As[buf][r0][k0 + tg + 4]);
                af[mt][3] = fb(As[buf][r0 + 8][k0 + tg + 4]);
            }
#pragma unroll
            for (int nt = 0; nt < 8; nt++) {
                int rn = wn + nt * 8 + g8;
                if (BMN) {
                    bf[nt][0] = fb(BsN[buf][k0 + tg][rn]);
                    bf[nt][1] = fb(BsN[buf][k0 + tg + 4][rn]);
                } else {
                    bf[nt][0] = fb(BsK[buf][rn][k0 + tg]);
                    bf[nt][1] = fb(BsK[buf][rn][k0 + tg + 4]);
                }
            }
#pragma unroll
            for (int mt = 0; mt < 4; mt++)
#pragma unroll
                for (int nt = 0; nt < 8; nt++)
                    mma8(F.a[mt][nt], af[mt], bf[nt]);
        }
        __syncthreads();
    }
}

// ---------------- prep: round W to tf32 --------------------------------------
__global__ __launch_bounds__(256) void prep_w(const float* __restrict__ Wq,
                                              const float* __restrict__ Wk,
                                              const float* __restrict__ Wd) {
    int idx = (blockIdx.x * 256 + threadIdx.x) * 4;       // over 3*262144
    int p = idx >> 18, off = idx & 262143;
    const float* W = (p == 0) ? Wq : (p == 1) ? Wk : Wd;
    float4 t = *(const float4*)(W + off);
    t.x = f2tf(t.x); t.y = f2tf(t.y); t.z = f2tf(t.z); t.w = f2tf(t.w);
    *(float4*)(g_W + idx) = t;
}

// ---------------- transpose x -> xt[(n*8+r)][f] (rounded) --------------------
__global__ __launch_bounds__(256) void transpose_x(const float* __restrict__ x) {
    __shared__ float s[512 * 9];
    const int n = blockIdx.x, tid = threadIdx.x;
    const float* src = x + (size_t)n * 4096;
#pragma unroll
    for (int i = 0; i < 4; i++) {
        int v = (tid + i * 256) * 4;
        float4 t = *(const float4*)(src + v);
        int f = v >> 3, rr = v & 7;
        s[f * 9 + rr + 0] = t.x; s[f * 9 + rr + 1] = t.y;
        s[f * 9 + rr + 2] = t.z; s[f * 9 + rr + 3] = t.w;
    }
    __syncthreads();
#pragma unroll
    for (int rr = 0; rr < 8; rr++)
#pragma unroll
        for (int q = 0; q < 2; q++) {
            int f = tid + q * 256;
            g_xt[((size_t)n * 8 + rr) * 512 + f] = f2tf(s[f * 9 + rr]);
        }
}

// ---------------- projection GEMM --------------------------------------------
__global__ __launch_bounds__(128) void proj_tc() {
    __shared__ float As[2][128][PADK], Bs[2][128][PADK];
    const int p = blockIdx.z;
    const int m0 = blockIdx.y * 128, c0 = blockIdx.x * 128;

    Acc F;
    gemm_main<0>(F, g_W + (size_t)p * HL * FEAT + (size_t)m0 * FEAT,
                 g_xt + (size_t)c0 * FEAT, FEAT, 0, As, Bs, nullptr);

    const int tid = threadIdx.x, lane = tid & 31, wid = tid >> 5;
    const int g8 = lane >> 2, tg = lane & 3;
    const int wm = (wid & 1) * 64, wn = (wid >> 1) * 64;
    float* base = g_Y + (size_t)p * HEAD * NE * 512;

#pragma unroll
    for (int mt = 0; mt < 4; mt++)
#pragma unroll
        for (int half = 0; half < 2; half++) {
            int row = m0 + wm + mt * 16 + g8 + half * 8;
            int hh = row >> 6, l = row & 63;
#pragma unroll
            for (int nt = 0; nt < 8; nt++) {
                int col = c0 + wn + nt * 8 + 2 * tg;
                int n = col >> 3, r = col & 7;
                float v0 = f2tf(F.a[mt][nt][half * 2 + 0]);
                float v1 = f2tf(F.a[mt][nt][half * 2 + 1]);
                *(float2*)(base + ((size_t)hh * NE + n) * 512 + l * 8 + r) = make_float2(v0, v1);
            }
        }
}

// ---------------- norms (all three projections) ------------------------------
__global__ __launch_bounds__(256) void norm_all() {
    const int n = blockIdx.x, p = blockIdx.y;
    float s = 0.f;
#pragma unroll
    for (int h = 0; h < HEAD; h++) {
        const float* rp = g_Y + (((size_t)p * HEAD + h) * NE + n) * 512;
#pragma unroll 2
        for (int j = threadIdx.x; j < 512; j += 256) { float v = rp[j]; s += v * v; }
    }
    __shared__ float red[256];
    red[threadIdx.x] = s;
    __syncthreads();
    for (int off = 128; off > 0; off >>= 1) {
        if (threadIdx.x < off) red[threadIdx.x] += red[threadIdx.x + off];
        __syncthreads();
    }
    if (threadIdx.x == 0) g_rn[p * NE + n] = rsqrtf(red[0]);
}

// ---------------- scores GEMM ------------------------------------------------
__global__ __launch_bounds__(128) void scores_tc() {
    __shared__ float As[2][128][PADK], Bs[2][128][PADK];
    const int h = blockIdx.z;
    const int m0 = blockIdx.y * 128, n0 = blockIdx.x * 128;

    Acc F;
    gemm_main<0>(F, g_Y + ((size_t)h * NE + m0) * 512,
                 g_Y + (((size_t)HEAD + h) * NE + n0) * 512, 512, 0, As, Bs, nullptr);

    const int tid = threadIdx.x, lane = tid & 31, wid = tid >> 5;
    const int g8 = lane >> 2, tg = lane & 3;
    const int wm = (wid & 1) * 64, wn = (wid >> 1) * 64;

#pragma unroll
    for (int mt = 0; mt < 4; mt++)
#pragma unroll
        for (int half = 0; half < 2; half++) {
            int row = m0 + wm + mt * 16 + g8 + half * 8;
            float rq = g_rn[row];
#pragma unroll
            for (int nt = 0; nt < 8; nt++) {
                int col = n0 + wn + nt * 8 + 2 * tg;
                float v0 = F.a[mt][nt][half * 2 + 0] * rq * g_rn[NE + col];
                float v1 = F.a[mt][nt][half * 2 + 1] * rq * g_rn[NE + col + 1];
                *(float2*)(g_S + ((size_t)h * NE + row) * NE + col) = make_float2(v0, v1);
            }
        }
}

// ---------------- softmax (folds 1/||d_m||, rounds weights) ------------------
__global__ __launch_bounds__(256) void softmax_kernel() {
    const int n = blockIdx.x, h = blockIdx.y;
    float* row = &g_S[((size_t)h * NE + n) * NE];
    const int tid = threadIdx.x;
    float e[8];
    float mx = -1e30f;
#pragma unroll
    for (int i = 0; i < 8; i++) { e[i] = row[tid + i * 256]; mx = fmaxf(mx, e[i]); }
    __shared__ float red[256];
    red[tid] = mx; __syncthreads();
    for (int off = 128; off > 0; off >>= 1) {
        if (tid < off) red[tid] = fmaxf(red[tid], red[tid + off]);
        __syncthreads();
    }
    mx = red[0]; __syncthreads();
    float s = 0.f;
#pragma unroll
    for (int i = 0; i < 8; i++) { e[i] = __expf(e[i] - mx); s += e[i]; }
    red[tid] = s; __syncthreads();
    for (int off = 128; off > 0; off >>= 1) {
        if (tid < off) red[tid] += red[tid + off];
        __syncthreads();
    }
    float inv = 1.0f / red[0];
#pragma unroll
    for (int i = 0; i < 8; i++) {
        int col = tid + i * 256;
        row[col] = f2tf(e[i] * inv * g_rn[2 * NE + col]);
    }
}

// ---------------- combine GEMM (B is MN-major: D[h][m][lr]) ------------------
__global__ __launch_bounds__(128) void combine_tc(float* __restrict__ out) {
    __shared__ float As[2][128][PADK];
    __shared__ float Bs[2][BK][PADN];
    const int h = blockIdx.z;
    const int m0 = blockIdx.y * 128, lr0 = blockIdx.x * 128;

    Acc F;
    gemm_main<1>(F, g_S + ((size_t)h * NE + m0) * NE,
                 g_Y + ((size_t)2 * HEAD + h) * NE * 512 + lr0, NE, 512,
                 As, nullptr, Bs);

    const int tid = threadIdx.x, lane = tid & 31, wid = tid >> 5;
    const int g8 = lane >> 2, tg = lane & 3;
    const int wm = (wid & 1) * 64, wn = (wid >> 1) * 64;

#pragma unroll
    for (int mt = 0; mt < 4; mt++)
#pragma unroll
        for (int half = 0; half < 2; half++) {
            int row = m0 + wm + mt * 16 + g8 + half * 8;
#pragma unroll
            for (int nt = 0; nt < 8; nt++) {
                int col = lr0 + wn + nt * 8 + 2 * tg;
                float v0 = F.a[mt][nt][half * 2 + 0];
                float v1 = F.a[mt][nt][half * 2 + 1];
                *(float2*)(out + (size_t)row * OUTC + h * 512 + col) = make_float2(v0, v1);
            }
        }
}

// ---------------------------------------------------------------------------
extern "C" void kernel_launch(void* const* d_in, const int* in_sizes, int n_in,
                              void* d_out, int out_size) {
    const float* x  = (const float*)d_in[0];
    const float* Wq = (const float*)d_in[1];
    const float* Wk = (const float*)d_in[2];
    const float* Wd = (const float*)d_in[3];
    float* out = (float*)d_out;

    prep_w<<<768, 256>>>(Wq, Wk, Wd);
    transpose_x<<<NE, 256>>>(x);
    proj_tc<<<dim3(NCOL / 128, HL / 128, 3), 128>>>();
    norm_all<<<dim3(NE, 3), 256>>>();
    scores_tc<<<dim3(NE / 128, NE / 128, HEAD), 128>>>();
    softmax_kernel<<<dim3(NE, HEAD), 256>>>();
    combine_tc<<<dim3(512 / 128, NE / 128, HEAD), 128>>>(out);
}

// round 5
// speedup vs baseline: 3.7963x; 1.0675x over previous
#include <cuda_runtime.h>
#include <math.h>
#include <stdint.h>

#define NE    2048
#define FEAT  512
#define REST  8
#define HEAD  8
#define HL    512
#define NCOL  16384
#define OUTC  (HEAD*512)
#define BK    16
#define PADK  20      // K-major tile row stride (20g+tg distinct mod 32)
#define PADN  136     // MN-major tile row stride

// ---------------- scratch ----------------------------------------------------
__device__ float g_Y  [(size_t)3 * HEAD * NE * 512];  // [p][h][n][lr], tf32-rounded
__device__ float g_xt [(size_t)NCOL * FEAT];          // xt[(n*8+r)][f], rounded
__device__ float g_W  [(size_t)3 * HL * FEAT];        // rounded weights
__device__ float g_S  [(size_t)HEAD * NE * NE];       // exp(scores)*rd, rounded
__device__ float g_ss [3 * NE];                       // sum of squares per (p, n)
__device__ float g_rs [(size_t)HEAD * NE];            // softmax row sums

// ---------------- helpers ----------------------------------------------------
__device__ __forceinline__ uint32_t smem_u32(const void* p) {
    uint32_t a;
    asm("{ .reg .u64 t; cvta.to.shared.u64 t, %1; cvt.u32.u64 %0, t; }" : "=r"(a) : "l"(p));
    return a;
}
__device__ __forceinline__ float f2tf(float f) {
    uint32_t u;
    asm("cvt.rna.tf32.f32 %0, %1;" : "=r"(u) : "f"(f));
    return __uint_as_float(u);
}
__device__ __forceinline__ void mma8(float* c, const uint32_t* a, const uint32_t* b) {
    asm volatile(
        "mma.sync.aligned.m16n8k8.row.col.f32.tf32.tf32.f32 "
        "{%0,%1,%2,%3}, {%4,%5,%6,%7}, {%8,%9}, {%0,%1,%2,%3};"
        : "+f"(c[0]), "+f"(c[1]), "+f"(c[2]), "+f"(c[3])
        : "r"(a[0]), "r"(a[1]), "r"(a[2]), "r"(a[3]), "r"(b[0]), "r"(b[1]));
}
__device__ __forceinline__ void cp16(uint32_t dst, const float* src) {
    uint64_t g;
    asm("cvta.to.global.u64 %0, %1;" : "=l"(g) : "l"(src));
    asm volatile("cp.async.cg.shared.global [%0], [%1], 16;" :: "r"(dst), "l"(g));
}
__device__ __forceinline__ uint32_t fb(float f) { return __float_as_uint(f); }

__device__ __forceinline__ void ld_k(float (*S)[PADK], const float* gp, int ldk, int k0, int tid) {
#pragma unroll
    for (int i = 0; i < 4; i++) {
        int idx = tid + i * 128;
        int row = idx >> 2, ch = idx & 3;
        cp16(smem_u32(&S[row][ch * 4]), gp + (size_t)row * ldk + k0 + ch * 4);
    }
}
__device__ __forceinline__ void ld_mn(float (*S)[PADN], const float* gp, int ldn, int k0, int tid) {
#pragma unroll
    for (int i = 0; i < 4; i++) {
        int idx = tid + i * 128;
        int kk = idx >> 5, ch = idx & 31;
        cp16(smem_u32(&S[kk][ch * 4]), gp + (size_t)(k0 + kk) * ldn + ch * 4);
    }
}

struct Acc { float a[4][8][4]; };

template<int BMN>
__device__ __forceinline__ void gemm_main(Acc& F, const float* A, const float* B,
                                          int K, int ldb,
                                          float (*As)[128][PADK],
                                          float (*BsK)[128][PADK],
                                          float (*BsN)[BK][PADN]) {
    const int tid = threadIdx.x;
    const int lane = tid & 31, wid = tid >> 5;
    const int g8 = lane >> 2, tg = lane & 3;
    const int wm = (wid & 1) * 64, wn = (wid >> 1) * 64;

#pragma unroll
    for (int mt = 0; mt < 4; mt++)
#pragma unroll
        for (int nt = 0; nt < 8; nt++)
#pragma unroll
            for (int j = 0; j < 4; j++) F.a[mt][nt][j] = 0.f;

    ld_k(As[0], A, K, 0, tid);
    if (BMN) ld_mn(BsN[0], B, ldb, 0, tid); else ld_k(BsK[0], B, K, 0, tid);
    asm volatile("cp.async.commit_group;" ::: "memory");

    const int KT = K / BK;
    for (int kt = 0; kt < KT; kt++) {
        int buf = kt & 1;
        if (kt + 1 < KT) {
            ld_k(As[buf ^ 1], A, K, (kt + 1) * BK, tid);
            if (BMN) ld_mn(BsN[buf ^ 1], B, ldb, (kt + 1) * BK, tid);
            else     ld_k(BsK[buf ^ 1], B, K, (kt + 1) * BK, tid);
            asm volatile("cp.async.commit_group;" ::: "memory");
            asm volatile("cp.async.wait_group 1;" ::: "memory");
        } else {
            asm volatile("cp.async.wait_group 0;" ::: "memory");
        }
        __syncthreads();

#pragma unroll
        for (int ks = 0; ks < 2; ks++) {
            const int k0 = ks * 8;
            uint32_t af[4][4], bf[8][2];
#pragma unroll
            for (int mt = 0; mt < 4; mt++) {
                int r0 = wm + mt * 16 + g8;
                af[mt][0] = fb(As[buf][r0][k0 + tg]);
                af[mt][1] = fb(As[buf][r0 + 8][k0 + tg]);
                af[mt][2] = fb(As[buf][r0][k0 + tg + 4]);
                af[mt][3] = fb(As[buf][r0 + 8][k0 + tg + 4]);
            }
#pragma unroll
            for (int nt = 0; nt < 8; nt++) {
                int rn = wn + nt * 8 + g8;
                if (BMN) {
                    bf[nt][0] = fb(BsN[buf][k0 + tg][rn]);
                    bf[nt][1] = fb(BsN[buf][k0 + tg + 4][rn]);
                } else {
                    bf[nt][0] = fb(BsK[buf][rn][k0 + tg]);
                    bf[nt][1] = fb(BsK[buf][rn][k0 + tg + 4]);
                }
            }
#pragma unroll
            for (int mt = 0; mt < 4; mt++)
#pragma unroll
                for (int nt = 0; nt < 8; nt++)
                    mma8(F.a[mt][nt], af[mt], bf[nt]);
        }
        __syncthreads();
    }
}

// ---------------- init: zero accumulators ------------------------------------
__global__ __launch_bounds__(256) void init_zero() {
    int i = blockIdx.x * 256 + threadIdx.x;
    if (i < 3 * NE) g_ss[i] = 0.f;
    if (i < HEAD * NE) g_rs[i] = 0.f;
}

// ---------------- prep: round W ----------------------------------------------
__global__ __launch_bounds__(256) void prep_w(const float* __restrict__ Wq,
                                              const float* __restrict__ Wk,
                                              const float* __restrict__ Wd) {
    int idx = (blockIdx.x * 256 + threadIdx.x) * 4;
    int p = idx >> 18, off = idx & 262143;
    const float* W = (p == 0) ? Wq : (p == 1) ? Wk : Wd;
    float4 t = *(const float4*)(W + off);
    t.x = f2tf(t.x); t.y = f2tf(t.y); t.z = f2tf(t.z); t.w = f2tf(t.w);
    *(float4*)(g_W + idx) = t;
}

// ---------------- transpose x -> xt ------------------------------------------
__global__ __launch_bounds__(256) void transpose_x(const float* __restrict__ x) {
    __shared__ float s[512 * 9];
    const int n = blockIdx.x, tid = threadIdx.x;
    const float* src = x + (size_t)n * 4096;
#pragma unroll
    for (int i = 0; i < 4; i++) {
        int v = (tid + i * 256) * 4;
        float4 t = *(const float4*)(src + v);
        int f = v >> 3, rr = v & 7;
        s[f * 9 + rr + 0] = t.x; s[f * 9 + rr + 1] = t.y;
        s[f * 9 + rr + 2] = t.z; s[f * 9 + rr + 3] = t.w;
    }
    __syncthreads();
#pragma unroll
    for (int rr = 0; rr < 8; rr++)
#pragma unroll
        for (int q = 0; q < 2; q++) {
            int f = tid + q * 256;
            g_xt[((size_t)n * 8 + rr) * 512 + f] = f2tf(s[f * 9 + rr]);
        }
}

// ---------------- projection GEMM + fused sum-of-squares --------------------
__global__ __launch_bounds__(128) void proj_tc() {
    __shared__ float As[2][128][PADK], Bs[2][128][PADK];
    __shared__ float csum[128];
    const int p = blockIdx.z;
    const int m0 = blockIdx.y * 128, c0 = blockIdx.x * 128;

    Acc F;
    gemm_main<0>(F, g_W + (size_t)p * HL * FEAT + (size_t)m0 * FEAT,
                 g_xt + (size_t)c0 * FEAT, FEAT, 0, As, Bs, nullptr);

    const int tid = threadIdx.x, lane = tid & 31, wid = tid >> 5;
    const int g8 = lane >> 2, tg = lane & 3;
    const int wm = (wid & 1) * 64, wn = (wid >> 1) * 64;
    float* base = g_Y + (size_t)p * HEAD * NE * 512;

    csum[tid] = 0.f;
    __syncthreads();

    float sq[8];
#pragma unroll
    for (int nt = 0; nt < 8; nt++) sq[nt] = 0.f;

#pragma unroll
    for (int mt = 0; mt < 4; mt++)
#pragma unroll
        for (int half = 0; half < 2; half++) {
            int row = m0 + wm + mt * 16 + g8 + half * 8;
            int hh = row >> 6, l = row & 63;
#pragma unroll
            for (int nt = 0; nt < 8; nt++) {
                int col = c0 + wn + nt * 8 + 2 * tg;
                int n = col >> 3, r = col & 7;
                float v0 = f2tf(F.a[mt][nt][half * 2 + 0]);
                float v1 = f2tf(F.a[mt][nt][half * 2 + 1]);
                *(float2*)(base + ((size_t)hh * NE + n) * 512 + l * 8 + r) = make_float2(v0, v1);
                sq[nt] += v0 * v0 + v1 * v1;
            }
        }
    // reduce over g8 (lanes stride 4); lanes 0..3 hold column-pair sums
#pragma unroll
    for (int nt = 0; nt < 8; nt++) {
        float v = sq[nt];
        v += __shfl_down_sync(0xffffffffu, v, 4);
        v += __shfl_down_sync(0xffffffffu, v, 8);
        v += __shfl_down_sync(0xffffffffu, v, 16);
        if (g8 == 0) atomicAdd(&csum[wn + nt * 8 + 2 * tg], v);  // v covers cols {col,col+1}
    }
    __syncthreads();
    if (tid < 16) {
        float s = 0.f;
#pragma unroll
        for (int j = 0; j < 8; j += 2) s += csum[tid * 8 + j];   // only even slots written
        atomicAdd(&g_ss[p * NE + (c0 >> 3) + tid], s);
    }
}

// ---------------- scores GEMM + fused exp/softmax-numerator -----------------
__global__ __launch_bounds__(128) void scores_tc() {
    __shared__ float As[2][128][PADK], Bs[2][128][PADK];
    __shared__ float rsum[128];
    const int h = blockIdx.z;
    const int m0 = blockIdx.y * 128, n0 = blockIdx.x * 128;

    Acc F;
    gemm_main<0>(F, g_Y + ((size_t)h * NE + m0) * 512,
                 g_Y + (((size_t)HEAD + h) * NE + n0) * 512, 512, 0, As, Bs, nullptr);

    const int tid = threadIdx.x, lane = tid & 31, wid = tid >> 5;
    const int g8 = lane >> 2, tg = lane & 3;
    const int wm = (wid & 1) * 64, wn = (wid >> 1) * 64;

    rsum[tid] = 0.f;
    __syncthreads();

    float rk[8][2], rd[8][2];
#pragma unroll
    for (int nt = 0; nt < 8; nt++) {
        int col = n0 + wn + nt * 8 + 2 * tg;
        rk[nt][0] = rsqrtf(g_ss[NE + col]);     rk[nt][1] = rsqrtf(g_ss[NE + col + 1]);
        rd[nt][0] = rsqrtf(g_ss[2 * NE + col]); rd[nt][1] = rsqrtf(g_ss[2 * NE + col + 1]);
    }

#pragma unroll
    for (int mt = 0; mt < 4; mt++)
#pragma unroll
        for (int half = 0; half < 2; half++) {
            int row = m0 + wm + mt * 16 + g8 + half * 8;
            float rq = rsqrtf(g_ss[row]);
            float rs = 0.f;
#pragma unroll
            for (int nt = 0; nt < 8; nt++) {
                int col = n0 + wn + nt * 8 + 2 * tg;
                float e0 = __expf(F.a[mt][nt][half * 2 + 0] * rq * rk[nt][0]);
                float e1 = __expf(F.a[mt][nt][half * 2 + 1] * rq * rk[nt][1]);
                rs += e0 + e1;
                float p0 = f2tf(e0 * rd[nt][0]);
                float p1 = f2tf(e1 * rd[nt][1]);
                *(float2*)(g_S + ((size_t)h * NE + row) * NE + col) = make_float2(p0, p1);
            }
            // reduce over tg (lanes stride 1,2); lane tg==0 holds row sum
            rs += __shfl_down_sync(0xffffffffu, rs, 1);
            rs += __shfl_down_sync(0xffffffffu, rs, 2);
            if (tg == 0) atomicAdd(&rsum[wm + mt * 16 + g8 + half * 8], rs);
        }
    __syncthreads();
    atomicAdd(&g_rs[(size_t)h * NE + m0 + tid], rsum[tid]);
}

// ---------------- combine GEMM (B MN-major), scale rows by 1/rowsum ---------
__global__ __launch_bounds__(128) void combine_tc(float* __restrict__ out) {
    __shared__ float As[2][128][PADK];
    __shared__ float Bs[2][BK][PADN];
    const int h = blockIdx.z;
    const int m0 = blockIdx.y * 128, lr0 = blockIdx.x * 128;

    Acc F;
    gemm_main<1>(F, g_S + ((size_t)h * NE + m0) * NE,
                 g_Y + ((size_t)2 * HEAD + h) * NE * 512 + lr0, NE, 512,
                 As, nullptr, Bs);

    const int tid = threadIdx.x, lane = tid & 31, wid = tid >> 5;
    const int g8 = lane >> 2, tg = lane & 3;
    const int wm = (wid & 1) * 64, wn = (wid >> 1) * 64;

#pragma unroll
    for (int mt = 0; mt < 4; mt++)
#pragma unroll
        for (int half = 0; half < 2; half++) {
            int row = m0 + wm + mt * 16 + g8 + half * 8;
            float inv = 1.0f / g_rs[(size_t)h * NE + row];
#pragma unroll
            for (int nt = 0; nt < 8; nt++) {
                int col = lr0 + wn + nt * 8 + 2 * tg;
                float v0 = F.a[mt][nt][half * 2 + 0] * inv;
                float v1 = F.a[mt][nt][half * 2 + 1] * inv;
                *(float2*)(out + (size_t)row * OUTC + h * 512 + col) = make_float2(v0, v1);
            }
        }
}

// ---------------------------------------------------------------------------
extern "C" void kernel_launch(void* const* d_in, const int* in_sizes, int n_in,
                              void* d_out, int out_size) {
    const float* x  = (const float*)d_in[0];
    const float* Wq = (const float*)d_in[1];
    const float* Wk = (const float*)d_in[2];
    const float* Wd = (const float*)d_in[3];
    float* out = (float*)d_out;

    init_zero<<<64, 256>>>();
    prep_w<<<768, 256>>>(Wq, Wk, Wd);
    transpose_x<<<NE, 256>>>(x);
    proj_tc<<<dim3(NCOL / 128, HL / 128, 3), 128>>>();
    scores_tc<<<dim3(NE / 128, NE / 128, HEAD), 128>>>();
    combine_tc<<<dim3(512 / 128, NE / 128, HEAD), 128>>>(out);
}

// round 6
// speedup vs baseline: 3.9343x; 1.0363x over previous
#include <cuda_runtime.h>
#include <math.h>
#include <stdint.h>

#define NE    2048
#define FEAT  512
#define REST  8
#define HEAD  8
#define HL    512
#define NCOL  16384
#define OUTC  (HEAD*512)
#define BK    16
#define PADK  20      // K-major tile row stride (20g+tg distinct mod 32)
#define PADN  136     // MN-major tile row stride
#define STG   3
#define ASTR  (128*PADK)
#define SMEM_BYTES (2 * STG * ASTR * 4)   // 61440

// ---------------- scratch ----------------------------------------------------
__device__ float g_Y  [(size_t)3 * HEAD * NE * 512];  // [p][h][n][lr], tf32-rounded
__device__ float g_xt [(size_t)NCOL * FEAT];          // xt[(n*8+r)][f], rounded
__device__ float g_W  [(size_t)3 * HL * FEAT];        // rounded weights
__device__ float g_S  [(size_t)HEAD * NE * NE];       // exp(scores)*rd, rounded
__device__ float g_ss [3 * NE];                       // sum of squares per (p, n)
__device__ float g_rs [(size_t)HEAD * NE];            // softmax row sums

// ---------------- helpers ----------------------------------------------------
__device__ __forceinline__ uint32_t smem_u32(const void* p) {
    uint32_t a;
    asm("{ .reg .u64 t; cvta.to.shared.u64 t, %1; cvt.u32.u64 %0, t; }" : "=r"(a) : "l"(p));
    return a;
}
__device__ __forceinline__ float f2tf(float f) {
    uint32_t u;
    asm("cvt.rna.tf32.f32 %0, %1;" : "=r"(u) : "f"(f));
    return __uint_as_float(u);
}
__device__ __forceinline__ void mma8(float* c, const uint32_t* a, const uint32_t* b) {
    asm volatile(
        "mma.sync.aligned.m16n8k8.row.col.f32.tf32.tf32.f32 "
        "{%0,%1,%2,%3}, {%4,%5,%6,%7}, {%8,%9}, {%0,%1,%2,%3};"
        : "+f"(c[0]), "+f"(c[1]), "+f"(c[2]), "+f"(c[3])
        : "r"(a[0]), "r"(a[1]), "r"(a[2]), "r"(a[3]), "r"(b[0]), "r"(b[1]));
}
__device__ __forceinline__ void cp16(uint32_t dst, const float* src) {
    uint64_t g;
    asm("cvta.to.global.u64 %0, %1;" : "=l"(g) : "l"(src));
    asm volatile("cp.async.cg.shared.global [%0], [%1], 16;" :: "r"(dst), "l"(g));
}
__device__ __forceinline__ uint32_t fb(float f) { return __float_as_uint(f); }

// 128 rows x 16 K-major tile into stage base S (row stride PADK)
__device__ __forceinline__ void ld_k(float* S, const float* gp, int ldk, int k0, int tid) {
#pragma unroll
    for (int i = 0; i < 4; i++) {
        int idx = tid + i * 128;
        int row = idx >> 2, ch = idx & 3;
        cp16(smem_u32(S + row * PADK + ch * 4), gp + (size_t)row * ldk + k0 + ch * 4);
    }
}
// 16 k-rows x 128 n-cols MN-major tile into stage base S (row stride PADN)
__device__ __forceinline__ void ld_mn(float* S, const float* gp, int ldn, int k0, int tid) {
#pragma unroll
    for (int i = 0; i < 4; i++) {
        int idx = tid + i * 128;
        int kk = idx >> 5, ch = idx & 31;
        cp16(smem_u32(S + kk * PADN + ch * 4), gp + (size_t)(k0 + kk) * ldn + ch * 4);
    }
}

struct Acc { float a[4][8][4]; };

// ---------------- 3-stage pipelined mainloop (one sync per BK tile) ----------
// BMN=0: B K-major [n][k]; BMN=1: B MN-major [k][n]
template<int BMN>
__device__ __forceinline__ void gemm_main(Acc& F, const float* A, const float* B,
                                          int K, int ldb, float* sA, float* sB) {
    const int tid = threadIdx.x;
    const int lane = tid & 31, wid = tid >> 5;
    const int g8 = lane >> 2, tg = lane & 3;
    const int wm = (wid & 1) * 64, wn = (wid >> 1) * 64;
    const int BSTR = BMN ? BK * PADN : 128 * PADK;

#pragma unroll
    for (int mt = 0; mt < 4; mt++)
#pragma unroll
        for (int nt = 0; nt < 8; nt++)
#pragma unroll
            for (int j = 0; j < 4; j++) F.a[mt][nt][j] = 0.f;

#pragma unroll
    for (int s = 0; s < STG - 1; s++) {
        ld_k(sA + s * ASTR, A, K, s * BK, tid);
        if (BMN) ld_mn(sB + s * BSTR, B, ldb, s * BK, tid);
        else     ld_k(sB + s * BSTR, B, K, s * BK, tid);
        asm volatile("cp.async.commit_group;" ::: "memory");
    }

    const int KT = K / BK;
    int ls = STG - 1;                 // next stage slot to fill
    for (int kt = 0; kt < KT; kt++) {
        asm volatile("cp.async.wait_group %0;" :: "n"(STG - 2) : "memory");
        __syncthreads();
        if (kt + STG - 1 < KT) {
            ld_k(sA + ls * ASTR, A, K, (kt + STG - 1) * BK, tid);
            if (BMN) ld_mn(sB + ls * BSTR, B, ldb, (kt + STG - 1) * BK, tid);
            else     ld_k(sB + ls * BSTR, B, K, (kt + STG - 1) * BK, tid);
            ls = (ls + 1 == STG) ? 0 : ls + 1;
        }
        asm volatile("cp.async.commit_group;" ::: "memory");   // empty at tail keeps count aligned

        int buf = kt % STG;
        const float* As = sA + buf * ASTR;
        const float* Bs = sB + buf * BSTR;
#pragma unroll
        for (int ks = 0; ks < 2; ks++) {
            const int k0 = ks * 8;
            uint32_t af[4][4], bf[8][2];
#pragma unroll
            for (int mt = 0; mt < 4; mt++) {
                int r0 = wm + mt * 16 + g8;
                af[mt][0] = fb(As[r0 * PADK + k0 + tg]);
                af[mt][1] = fb(As[(r0 + 8) * PADK + k0 + tg]);
                af[mt][2] = fb(As[r0 * PADK + k0 + tg + 4]);
                af[mt][3] = fb(As[(r0 + 8) * PADK + k0 + tg + 4]);
            }
#pragma unroll
            for (int nt = 0; nt < 8; nt++) {
                int rn = wn + nt * 8 + g8;
                if (BMN) {
                    bf[nt][0] = fb(Bs[(k0 + tg) * PADN + rn]);
                    bf[nt][1] = fb(Bs[(k0 + tg + 4) * PADN + rn]);
                } else {
                    bf[nt][0] = fb(Bs[rn * PADK + k0 + tg]);
                    bf[nt][1] = fb(Bs[rn * PADK + k0 + tg + 4]);
                }
            }
#pragma unroll
            for (int mt = 0; mt < 4; mt++)
#pragma unroll
                for (int nt = 0; nt < 8; nt++)
                    mma8(F.a[mt][nt], af[mt], bf[nt]);
        }
    }
    __syncthreads();
}

// ---------------- init / prep / transpose ------------------------------------
__global__ __launch_bounds__(256) void init_zero() {
    int i = blockIdx.x * 256 + threadIdx.x;
    if (i < 3 * NE) g_ss[i] = 0.f;
    if (i < HEAD * NE) g_rs[i] = 0.f;
}
__global__ __launch_bounds__(256) void prep_w(const float* __restrict__ Wq,
                                              const float* __restrict__ Wk,
                                              const float* __restrict__ Wd) {
    int idx = (blockIdx.x * 256 + threadIdx.x) * 4;
    int p = idx >> 18, off = idx & 262143;
    const float* W = (p == 0) ? Wq : (p == 1) ? Wk : Wd;
    float4 t = *(const float4*)(W + off);
    t.x = f2tf(t.x); t.y = f2tf(t.y); t.z = f2tf(t.z); t.w = f2tf(t.w);
    *(float4*)(g_W + idx) = t;
}
__global__ __launch_bounds__(256) void transpose_x(const float* __restrict__ x) {
    __shared__ float s[512 * 9];
    const int n = blockIdx.x, tid = threadIdx.x;
    const float* src = x + (size_t)n * 4096;
#pragma unroll
    for (int i = 0; i < 4; i++) {
        int v = (tid + i * 256) * 4;
        float4 t = *(const float4*)(src + v);
        int f = v >> 3, rr = v & 7;
        s[f * 9 + rr + 0] = t.x; s[f * 9 + rr + 1] = t.y;
        s[f * 9 + rr + 2] = t.z; s[f * 9 + rr + 3] = t.w;
    }
    __syncthreads();
#pragma unroll
    for (int rr = 0; rr < 8; rr++)
#pragma unroll
        for (int q = 0; q < 2; q++) {
            int f = tid + q * 256;
            g_xt[((size_t)n * 8 + rr) * 512 + f] = f2tf(s[f * 9 + rr]);
        }
}

// ---------------- projection GEMM + fused sum-of-squares --------------------
__global__ __launch_bounds__(128) void proj_tc() {
    extern __shared__ float dsm[];
    __shared__ float csum[128];
    float* sA = dsm;
    float* sB = dsm + STG * ASTR;
    const int p = blockIdx.z;
    const int m0 = blockIdx.y * 128, c0 = blockIdx.x * 128;

    const int tid = threadIdx.x, lane = tid & 31, wid = tid >> 5;
    const int g8 = lane >> 2, tg = lane & 3;
    const int wm = (wid & 1) * 64, wn = (wid >> 1) * 64;

    csum[tid] = 0.f;

    Acc F;
    gemm_main<0>(F, g_W + (size_t)p * HL * FEAT + (size_t)m0 * FEAT,
                 g_xt + (size_t)c0 * FEAT, FEAT, 0, sA, sB);

    float* base = g_Y + (size_t)p * HEAD * NE * 512;
    float sq[8];
#pragma unroll
    for (int nt = 0; nt < 8; nt++) sq[nt] = 0.f;

#pragma unroll
    for (int mt = 0; mt < 4; mt++)
#pragma unroll
        for (int half = 0; half < 2; half++) {
            int row = m0 + wm + mt * 16 + g8 + half * 8;
            int hh = row >> 6, l = row & 63;
#pragma unroll
            for (int nt = 0; nt < 8; nt++) {
                int col = c0 + wn + nt * 8 + 2 * tg;
                int n = col >> 3, r = col & 7;
                float v0 = f2tf(F.a[mt][nt][half * 2 + 0]);
                float v1 = f2tf(F.a[mt][nt][half * 2 + 1]);
                *(float2*)(base + ((size_t)hh * NE + n) * 512 + l * 8 + r) = make_float2(v0, v1);
                sq[nt] += v0 * v0 + v1 * v1;
            }
        }
#pragma unroll
    for (int nt = 0; nt < 8; nt++) {
        float v = sq[nt];
        v += __shfl_down_sync(0xffffffffu, v, 4);
        v += __shfl_down_sync(0xffffffffu, v, 8);
        v += __shfl_down_sync(0xffffffffu, v, 16);
        if (g8 == 0) atomicAdd(&csum[wn + nt * 8 + 2 * tg], v);
    }
    __syncthreads();
    if (tid < 16) {
        float s = 0.f;
#pragma unroll
        for (int j = 0; j < 8; j += 2) s += csum[tid * 8 + j];
        atomicAdd(&g_ss[p * NE + (c0 >> 3) + tid], s);
    }
}

// ---------------- scores GEMM + fused exp/softmax-numerator -----------------
__global__ __launch_bounds__(128) void scores_tc() {
    extern __shared__ float dsm[];
    __shared__ float rsum[128];
    float* sA = dsm;
    float* sB = dsm + STG * ASTR;
    const int h = blockIdx.z;
    const int m0 = blockIdx.y * 128, n0 = blockIdx.x * 128;

    const int tid = threadIdx.x, lane = tid & 31, wid = tid >> 5;
    const int g8 = lane >> 2, tg = lane & 3;
    const int wm = (wid & 1) * 64, wn = (wid >> 1) * 64;

    rsum[tid] = 0.f;

    Acc F;
    gemm_main<0>(F, g_Y + ((size_t)h * NE + m0) * 512,
                 g_Y + (((size_t)HEAD + h) * NE + n0) * 512, 512, 0, sA, sB);

    float rk[8][2], rd[8][2];
#pragma unroll
    for (int nt = 0; nt < 8; nt++) {
        int col = n0 + wn + nt * 8 + 2 * tg;
        rk[nt][0] = rsqrtf(g_ss[NE + col]);     rk[nt][1] = rsqrtf(g_ss[NE + col + 1]);
        rd[nt][0] = rsqrtf(g_ss[2 * NE + col]); rd[nt][1] = rsqrtf(g_ss[2 * NE + col + 1]);
    }

#pragma unroll
    for (int mt = 0; mt < 4; mt++)
#pragma unroll
        for (int half = 0; half < 2; half++) {
            int row = m0 + wm + mt * 16 + g8 + half * 8;
            float rq = rsqrtf(g_ss[row]);
            float rs = 0.f;
#pragma unroll
            for (int nt = 0; nt < 8; nt++) {
                int col = n0 + wn + nt * 8 + 2 * tg;
                float e0 = __expf(F.a[mt][nt][half * 2 + 0] * rq * rk[nt][0]);
                float e1 = __expf(F.a[mt][nt][half * 2 + 1] * rq * rk[nt][1]);
                rs += e0 + e1;
                float p0 = f2tf(e0 * rd[nt][0]);
                float p1 = f2tf(e1 * rd[nt][1]);
                *(float2*)(g_S + ((size_t)h * NE + row) * NE + col) = make_float2(p0, p1);
            }
            rs += __shfl_down_sync(0xffffffffu, rs, 1);
            rs += __shfl_down_sync(0xffffffffu, rs, 2);
            if (tg == 0) atomicAdd(&rsum[wm + mt * 16 + g8 + half * 8], rs);
        }
    __syncthreads();
    atomicAdd(&g_rs[(size_t)h * NE + m0 + tid], rsum[tid]);
}

// ---------------- combine GEMM (B MN-major), scale rows by 1/rowsum ---------
__global__ __launch_bounds__(128) void combine_tc(float* __restrict__ out) {
    extern __shared__ float dsm[];
    float* sA = dsm;
    float* sB = dsm + STG * ASTR;
    const int h = blockIdx.z;
    const int m0 = blockIdx.y * 128, lr0 = blockIdx.x * 128;

    Acc F;
    gemm_main<1>(F, g_S + ((size_t)h * NE + m0) * NE,
                 g_Y + ((size_t)2 * HEAD + h) * NE * 512 + lr0, NE, 512, sA, sB);

    const int tid = threadIdx.x, lane = tid & 31, wid = tid >> 5;
    const int g8 = lane >> 2, tg = lane & 3;
    const int wm = (wid & 1) * 64, wn = (wid >> 1) * 64;

#pragma unroll
    for (int mt = 0; mt < 4; mt++)
#pragma unroll
        for (int half = 0; half < 2; half++) {
            int row = m0 + wm + mt * 16 + g8 + half * 8;
            float inv = 1.0f / g_rs[(size_t)h * NE + row];
#pragma unroll
            for (int nt = 0; nt < 8; nt++) {
                int col = lr0 + wn + nt * 8 + 2 * tg;
                float v0 = F.a[mt][nt][half * 2 + 0] * inv;
                float v1 = F.a[mt][nt][half * 2 + 1] * inv;
                *(float2*)(out + (size_t)row * OUTC + h * 512 + col) = make_float2(v0, v1);
            }
        }
}

// ---------------------------------------------------------------------------
extern "C" void kernel_launch(void* const* d_in, const int* in_sizes, int n_in,
                              void* d_out, int out_size) {
    const float* x  = (const float*)d_in[0];
    const float* Wq = (const float*)d_in[1];
    const float* Wk = (const float*)d_in[2];
    const float* Wd = (const float*)d_in[3];
    float* out = (float*)d_out;

    cudaFuncSetAttribute(proj_tc,    cudaFuncAttributeMaxDynamicSharedMemorySize, SMEM_BYTES);
    cudaFuncSetAttribute(scores_tc,  cudaFuncAttributeMaxDynamicSharedMemorySize, SMEM_BYTES);
    cudaFuncSetAttribute(combine_tc, cudaFuncAttributeMaxDynamicSharedMemorySize, SMEM_BYTES);

    init_zero<<<64, 256>>>();
    prep_w<<<768, 256>>>(Wq, Wk, Wd);
    transpose_x<<<NE, 256>>>(x);
    proj_tc<<<dim3(NCOL / 128, HL / 128, 3), 128, SMEM_BYTES>>>();
    scores_tc<<<dim3(NE / 128, NE / 128, HEAD), 128, SMEM_BYTES>>>();
    combine_tc<<<dim3(512 / 128, NE / 128, HEAD), 128, SMEM_BYTES>>>(out);
}